// round 13
// baseline (speedup 1.0000x reference)
#include <cuda_runtime.h>
#include <cuda_bf16.h>
#include <cstdint>
#include <math.h>

#define BB 64
#define SS 512
#define EE 256
#define HH 512
#define HDI 1024
#define G4 2048              // 4*H
#define NG 4096              // 2 dirs * 4H
#define TT 9
#define MR (BB*SS)           // 32768 rows

typedef __nv_bfloat16 bf16;

// ---------------- static device buffers ----------------
__device__ __align__(256) bf16  d_x0h[(size_t)MR * EE];
__device__ __align__(256) bf16  d_x0l[(size_t)MR * EE];
__device__ __align__(256) bf16  d_w0h[(size_t)NG * EE];
__device__ __align__(256) bf16  d_w0l[(size_t)NG * EE];
__device__ __align__(256) bf16  d_w1h[(size_t)NG * HDI];
__device__ __align__(256) bf16  d_w1l[(size_t)NG * HDI];
__device__ __align__(256) float d_xg0[(size_t)2 * SS * BB * G4];
__device__ __align__(256) float d_xg1[(size_t)2 * SS * BB * G4];
__device__ __align__(256) bf16  d_x1h[(size_t)MR * HDI];
__device__ __align__(256) bf16  d_x1l[(size_t)MR * HDI];
__device__ __align__(256) float d_x2[(size_t)MR * HDI];
__device__ __align__(256) bf16  d_hbh[2 * 2 * BB * HH];    // [dir][pp][m][k]
__device__ __align__(256) bf16  d_hbl[2 * 2 * BB * HH];
__device__ __align__(256) float d_logits[(size_t)MR * TT];
__device__ float d_llh[BB];
// two-level barrier state: 8 leaves x 8 blocks per dir + 1 root per dir
__device__ __align__(256) unsigned g_lcnt[2 * 8 * 32];
__device__ __align__(256) unsigned g_lgen[2 * 8 * 32];
__device__ __align__(256) unsigned g_rcnt[2 * 32];
__device__ __align__(256) unsigned g_rgen[2 * 32];

// ---------------- helpers ----------------
__device__ __forceinline__ void split_bf(float x, bf16 &h, bf16 &l) {
    h = __float2bfloat16(x);
    l = __float2bfloat16(x - __bfloat162float(h));
}
__device__ __forceinline__ unsigned pack2(bf16 a, bf16 b) {
    __nv_bfloat162 v; v.x = a; v.y = b;
    return *(unsigned*)&v;
}
__device__ __forceinline__ void mma_bf16(float* c, unsigned a0, unsigned a1,
                                         unsigned a2, unsigned a3,
                                         unsigned b0, unsigned b1) {
    asm volatile(
        "mma.sync.aligned.m16n8k16.row.col.f32.bf16.bf16.f32 "
        "{%0,%1,%2,%3}, {%4,%5,%6,%7}, {%8,%9}, {%0,%1,%2,%3};"
        : "+f"(c[0]), "+f"(c[1]), "+f"(c[2]), "+f"(c[3])
        : "r"(a0), "r"(a1), "r"(a2), "r"(a3), "r"(b0), "r"(b1));
}
#define LDSM4(r0, r1, r2, r3, addr) \
    asm volatile("ldmatrix.sync.aligned.m8n8.x4.shared.b16 {%0,%1,%2,%3}, [%4];" \
        : "=r"(r0), "=r"(r1), "=r"(r2), "=r"(r3) : "r"(addr))
#define CPA16(dst_u32, src) \
    asm volatile("cp.async.cg.shared.global [%0], [%1], 16;" :: "r"(dst_u32), "l"(src))
#define CP_COMMIT() asm volatile("cp.async.commit_group;")
#define CP_WAIT1()  asm volatile("cp.async.wait_group 1;")
#define CP_WAIT0()  asm volatile("cp.async.wait_group 0;")

// ---------------- two-level grid barrier (per dir: 8 leaves x 8 blocks) ----------------
__device__ __forceinline__ void grid_barrier_d(int d, int blk) {
    __syncthreads();
    if (threadIdx.x == 0) {
        const int leaf = blk >> 3;
        unsigned* lcnt = &g_lcnt[(d * 8 + leaf) * 32];
        unsigned* lgen = &g_lgen[(d * 8 + leaf) * 32];
        unsigned* rcnt = &g_rcnt[d * 32];
        unsigned* rgen = &g_rgen[d * 32];
        __threadfence();
        unsigned lg = atomicAdd(lgen, 0u);
        unsigned lr = atomicAdd(lcnt, 1u);
        if (lr == 7u) {                      // last in leaf -> go to root
            atomicExch(lcnt, 0u);
            unsigned rg = atomicAdd(rgen, 0u);
            unsigned rr = atomicAdd(rcnt, 1u);
            if (rr == 7u) {                  // last leaf -> release root
                atomicExch(rcnt, 0u);
                __threadfence();
                atomicAdd(rgen, 1u);
            } else {
                while (atomicAdd(rgen, 0u) == rg) { __nanosleep(32); }
            }
            __threadfence();
            atomicAdd(lgen, 1u);             // release my leaf
        } else {
            while (atomicAdd(lgen, 0u) == lg) { __nanosleep(32); }
        }
        __threadfence();
    }
    __syncthreads();
}

// ---------------- embedding gather + bf16 split ----------------
__global__ void k_embed(const int* __restrict__ ids, const float* __restrict__ emb) {
    int row = blockIdx.x;
    int tid = threadIdx.x;                    // 64 threads, 4 cols each
    const float4* src = (const float4*)(emb + (size_t)ids[row] * EE);
    float4 v = src[tid];
    bf16 h0, l0, h1, l1, h2, l2, h3, l3;
    split_bf(v.x, h0, l0); split_bf(v.y, h1, l1);
    split_bf(v.z, h2, l2); split_bf(v.w, h3, l3);
    size_t o = (size_t)row * EE + 4 * tid;
    *(unsigned*)&d_x0h[o]     = pack2(h0, h1);
    *(unsigned*)&d_x0h[o + 2] = pack2(h2, h3);
    *(unsigned*)&d_x0l[o]     = pack2(l0, l1);
    *(unsigned*)&d_x0l[o + 2] = pack2(l2, l3);
}

// ---------------- weight split ----------------
__global__ void k_split(const float* __restrict__ src, bf16* __restrict__ h,
                        bf16* __restrict__ l, int n) {
    int i = blockIdx.x * blockDim.x + threadIdx.x;
    if (i < n) { bf16 a, b; split_bf(src[i], a, b); h[i] = a; l[i] = b; }
}

// ---------------- input-projection GEMM (3xBF16 mma + ldmatrix, 128x256 tile) ----------------
// Block 128(m) x 256(n), Kt=32, 16 warps (2x8), warp tile 64x32.
// Stage layout (rows x GST): Ah[128] Al[128] Wh[256] Wl[256] = 768 rows.
#define GST 40                                   // smem row stride (bf16 elems)
#define GSTAGE (768 * GST)                       // elems per stage
template <int PH>
__global__ void __launch_bounds__(512) k_gemm(const float* __restrict__ bih,
                                              const float* __restrict__ bhh) {
    constexpr int K = (PH == 0) ? EE : HDI;
    const bf16* Ah = (PH == 0) ? d_x0h : d_x1h;
    const bf16* Al = (PH == 0) ? d_x0l : d_x1l;
    const bf16* Wh = (PH == 0) ? d_w0h : d_w1h;
    const bf16* Wl = (PH == 0) ? d_w0l : d_w1l;
    float* xg      = (PH == 0) ? d_xg0 : d_xg1;

    extern __shared__ bf16 sm[];
    const unsigned sm_u32 = (unsigned)__cvta_generic_to_shared(sm);

    const int m0 = blockIdx.y * 128;
    const int n0 = blockIdx.x * 256;
    const int tid = threadIdx.x;
    const int wid = tid >> 5;
    const int lane = tid & 31;
    const int wm = (wid >> 3) * 64;              // 2 m-groups of 64
    const int wn = (wid & 7) * 32;               // 8 n-tiles of 32

    // ldmatrix lane offsets (bytes)
    const unsigned laneA = (((lane & 7) + ((lane >> 3) & 1) * 8) * GST + (lane >> 4) * 8) * 2;
    const unsigned laneB = (((lane & 7) + (lane >> 4) * 8) * GST + ((lane >> 3) & 1) * 8) * 2;

    float acc[4][4][4];
#pragma unroll
    for (int i = 0; i < 4; i++)
#pragma unroll
        for (int j = 0; j < 4; j++)
#pragma unroll
            for (int q = 0; q < 4; q++) acc[i][j][q] = 0.f;

    const bf16* gsrc[4] = {Ah, Al, Wh, Wl};
    const int rowbase[4] = {m0, m0, n0, n0};
    const int arrbase[4] = {0, 128 * GST, 256 * GST, 512 * GST};

    auto stage = [&](int s, int k0) {
#pragma unroll
        for (int i = 0; i < 6; i++) {
            int slot = tid + 512 * i;            // 0..3071
            int gr = slot >> 2;                  // 0..767
            int seg = slot & 3;
            int q = gr >> 7;                     // 0..5
            int arr = (q < 2) ? q : (q < 4) ? 2 : 3;
            int row = (q < 2) ? (gr & 127) : (gr & 255);
            const bf16* src = gsrc[arr] + (size_t)(rowbase[arr] + row) * K + k0 + seg * 8;
            unsigned dst = sm_u32 + (unsigned)((s * GSTAGE + arrbase[arr] + row * GST + seg * 8) * 2);
            CPA16(dst, src);
        }
        CP_COMMIT();
    };

    constexpr int KT = K / 32;
    stage(0, 0);
    stage(1, 32);
    for (int it = 0; it < KT; it++) {
        if (it + 1 < KT) { CP_WAIT1(); } else { CP_WAIT0(); }
        __syncthreads();
        if (it + 2 < KT) stage((it + 2) % 3, (it + 2) * 32);

        const unsigned sbase = sm_u32 + (unsigned)((it % 3) * GSTAGE * 2);
        const unsigned aAh = sbase + (unsigned)(wm * GST * 2) + laneA;
        const unsigned aAl = aAh + (unsigned)(128 * GST * 2);
        const unsigned aWh = sbase + (unsigned)(256 * GST * 2) + (unsigned)(wn * GST * 2) + laneB;
        const unsigned aWl = aWh + (unsigned)(256 * GST * 2);

#pragma unroll
        for (int kk = 0; kk < 32; kk += 16) {
            unsigned ah[4][4], al[4][4], bh[2][4], bl[2][4];
#pragma unroll
            for (int mi = 0; mi < 4; mi++) {
                unsigned off = (unsigned)(mi * 16 * GST * 2 + kk * 2);
                LDSM4(ah[mi][0], ah[mi][1], ah[mi][2], ah[mi][3], aAh + off);
                LDSM4(al[mi][0], al[mi][1], al[mi][2], al[mi][3], aAl + off);
            }
#pragma unroll
            for (int np = 0; np < 2; np++) {
                unsigned off = (unsigned)(np * 16 * GST * 2 + kk * 2);
                LDSM4(bh[np][0], bh[np][1], bh[np][2], bh[np][3], aWh + off);
                LDSM4(bl[np][0], bl[np][1], bl[np][2], bl[np][3], aWl + off);
            }
#pragma unroll
            for (int np = 0; np < 2; np++)
#pragma unroll
                for (int j = 0; j < 2; j++) {
                    int ni = np * 2 + j;
                    unsigned b0h = bh[np][2 * j], b1h = bh[np][2 * j + 1];
                    unsigned b0l = bl[np][2 * j], b1l = bl[np][2 * j + 1];
#pragma unroll
                    for (int mi = 0; mi < 4; mi++) {
                        mma_bf16(acc[mi][ni], ah[mi][0], ah[mi][1], ah[mi][2], ah[mi][3], b0h, b1h);
                        mma_bf16(acc[mi][ni], ah[mi][0], ah[mi][1], ah[mi][2], ah[mi][3], b0l, b1l);
                        mma_bf16(acc[mi][ni], al[mi][0], al[mi][1], al[mi][2], al[mi][3], b0h, b1h);
                    }
                }
        }
    }

    // epilogue: bias + scatter to xg[d][s][b][gate]
    const int fr2 = lane >> 2;
    const int fc2 = lane & 3;
#pragma unroll
    for (int ni = 0; ni < 4; ni++) {
        int ncol = n0 + wn + ni * 8 + 2 * fc2;
        float bias0 = bih[ncol] + bhh[ncol];
        float bias1 = bih[ncol + 1] + bhh[ncol + 1];
        int d = ncol >> 11;
        int gate = ncol & 2047;
#pragma unroll
        for (int mi = 0; mi < 4; mi++) {
#pragma unroll
            for (int half = 0; half < 2; half++) {
                int m = m0 + wm + mi * 16 + fr2 + half * 8;
                int b = m >> 9;
                int s = m & 511;
                float2 v;
                v.x = acc[mi][ni][half * 2 + 0] + bias0;
                v.y = acc[mi][ni][half * 2 + 1] + bias1;
                *(float2*)(xg + ((size_t)(d * SS + s) * BB + b) * G4 + gate) = v;
            }
        }
    }
}

// ---------------- persistent bidirectional LSTM scan (ldmatrix + 3-slot pipeline) ----------------
// 128 blocks: (dir, 8 hidden units). 128 threads (4 warps).
// Per step: G[64b][32c] = h[64][512] @ Wslice^T via m16n8k16, gates in-register.
// 4 chunks of k=128 in 3 rotating smem slots; 4 syncthreads/step.
#define WST 520                                  // ws row stride
#define CST 136                                  // chunk row stride (128 + 8 pad)
#define WS_ELEMS (32 * WST)
#define CH_ELEMS (64 * CST)
template <int PH>
__global__ void __launch_bounds__(128, 1) k_scan(const float* __restrict__ whh, int nb) {
    extern __shared__ bf16 sm[];
    bf16* wsh = sm;                              // [32][WST]  c = g*8 + jj ordering
    bf16* wsl = sm + WS_ELEMS;
    const unsigned ws_u32 = (unsigned)__cvta_generic_to_shared(sm);
    const unsigned chk_u32 = ws_u32 + (unsigned)(2 * WS_ELEMS * 2);

    const float* xg = (PH == 0) ? d_xg0 : d_xg1;

    const int tid = threadIdx.x;
    const int d = blockIdx.x >> 6;
    const int blk = blockIdx.x & 63;
    const int j0 = blk * 8;

    // preload recurrent weight slice: ws[c][k], c = g*8 + jj
    for (int idx = tid; idx < 32 * HH; idx += 128) {
        int c = idx >> 9;
        int k = idx & 511;
        int g = c >> 3, jj = c & 7;
        float w = whh[((size_t)d * G4 + (size_t)g * HH + j0 + jj) * HH + k];
        bf16 h, l; split_bf(w, h, l);
        wsh[c * WST + k] = h;
        wsl[c * WST + k] = l;
    }
    // zero ping h (pp=0) for this block's 8 columns
    for (int idx = tid; idx < 64 * 4; idx += 128) {
        int m = idx >> 2, q = idx & 3;
        *(unsigned*)&d_hbh[((size_t)(d * 2 + 0) * BB + m) * HH + j0 + 2 * q] = 0u;
        *(unsigned*)&d_hbl[((size_t)(d * 2 + 0) * BB + m) * HH + j0 + 2 * q] = 0u;
    }
    grid_barrier_d(d, blk);

    const int lane = tid & 31;
    const int w = tid >> 5;
    const int fr = lane >> 2;
    const int fc = lane & 3;
    const int m1 = w * 16 + fr;                  // rows m1, m1+8
    const int u0 = 2 * fc;                       // units u0, u0+1

    // ldmatrix lane offsets (bytes)
    const unsigned laneA = (((lane & 7) + ((lane >> 3) & 1) * 8) * CST + (lane >> 4) * 8) * 2;
    const unsigned laneB = (((lane & 7) + (lane >> 4) * 8) * WST + ((lane >> 3) & 1) * 8) * 2;
    const unsigned aAbase = chk_u32 + (unsigned)(w * 16 * CST * 2) + laneA;

    float creg[4] = {0.f, 0.f, 0.f, 0.f};

    for (int t = 0; t < SS; t++) {
        const int tt = d ? (SS - 1 - t) : t;
        const bf16* hsh = d_hbh + ((size_t)(d * 2 + (t & 1)) * BB) * HH;
        const bf16* hsl = d_hbl + ((size_t)(d * 2 + (t & 1)) * BB) * HH;

        // stage chunk c into slot s: 2048 copies, 16 per thread
        auto stg = [&](int s, int c) {
            int k0 = c * 128;
            unsigned sb = chk_u32 + (unsigned)(s * 2 * CH_ELEMS * 2);
#pragma unroll
            for (int i = 0; i < 16; i++) {
                int slot = tid + 128 * i;        // 0..2047
                int arr = slot >> 10;            // 0: hi, 1: lo
                int wi = slot & 1023;
                int row = wi >> 4;               // 0..63
                int seg = wi & 15;               // k = k0 + seg*8
                const bf16* src = (arr ? hsl : hsh) + (size_t)row * HH + k0 + seg * 8;
                unsigned dst = sb + (unsigned)((arr * CH_ELEMS + row * CST + seg * 8) * 2);
                CPA16(dst, src);
            }
            CP_COMMIT();
        };
        stg(0, 0);
        stg(1, 1);

        // prefetch xg (independent of h)
        const float* xb = xg + (((size_t)d * SS + tt) * BB + m1) * G4 + j0 + u0;
        float2 xv[8];
#pragma unroll
        for (int g = 0; g < 4; g++) {
            xv[g * 2 + 0] = *(const float2*)(xb + (size_t)g * HH);
            xv[g * 2 + 1] = *(const float2*)(xb + (size_t)g * HH + (size_t)8 * G4);
        }

        float acc[4][4];
#pragma unroll
        for (int g = 0; g < 4; g++)
#pragma unroll
            for (int q = 0; q < 4; q++) acc[g][q] = 0.f;

        for (int c = 0; c < 4; c++) {
            if (c < 3) { CP_WAIT1(); } else { CP_WAIT0(); }
            __syncthreads();
            if (c + 2 < 4) stg((c + 2) % 3, c + 2);

            const unsigned aA = aAbase + (unsigned)((c % 3) * 2 * CH_ELEMS * 2);
            const unsigned aWb = ws_u32 + (unsigned)(c * 128 * 2) + laneB;
#pragma unroll
            for (int kk = 0; kk < 128; kk += 16) {
                unsigned a0, a1, a2, a3, c0, c1, c2, c3;
                LDSM4(a0, a1, a2, a3, aA + (unsigned)(kk * 2));
                LDSM4(c0, c1, c2, c3, aA + (unsigned)(CH_ELEMS * 2 + kk * 2));
#pragma unroll
                for (int np = 0; np < 2; np++) {
                    unsigned bh0, bh1, bh2, bh3, bl0, bl1, bl2, bl3;
                    unsigned off = (unsigned)(np * 16 * WST * 2 + kk * 2);
                    LDSM4(bh0, bh1, bh2, bh3, aWb + off);
                    LDSM4(bl0, bl1, bl2, bl3, aWb + (unsigned)(WS_ELEMS * 2) + off);
                    int n0i = np * 2;
                    mma_bf16(acc[n0i], a0, a1, a2, a3, bh0, bh1);
                    mma_bf16(acc[n0i], a0, a1, a2, a3, bl0, bl1);
                    mma_bf16(acc[n0i], c0, c1, c2, c3, bh0, bh1);
                    mma_bf16(acc[n0i + 1], a0, a1, a2, a3, bh2, bh3);
                    mma_bf16(acc[n0i + 1], a0, a1, a2, a3, bl2, bl3);
                    mma_bf16(acc[n0i + 1], c0, c1, c2, c3, bh2, bh3);
                }
            }
        }

        // gates: cell q -> (row m1 + 8*(q>>1), unit u0 + (q&1)), acc[g][q]
        float hn[4];
#pragma unroll
        for (int q = 0; q < 4; q++) {
            int rh = q >> 1;
            float xi = (q & 1) ? xv[0 + rh].y : xv[0 + rh].x;
            float xf = (q & 1) ? xv[2 + rh].y : xv[2 + rh].x;
            float xgv = (q & 1) ? xv[4 + rh].y : xv[4 + rh].x;
            float xo = (q & 1) ? xv[6 + rh].y : xv[6 + rh].x;
            float vi = acc[0][q] + xi;
            float vf = acc[1][q] + xf;
            float vg = acc[2][q] + xgv;
            float vo = acc[3][q] + xo;
            float si = 1.f / (1.f + expf(-vi));
            float sf = 1.f / (1.f + expf(-vf));
            float so = 1.f / (1.f + expf(-vo));
            float tg = tanhf(vg);
            creg[q] = sf * creg[q] + si * tg;
            hn[q] = so * tanhf(creg[q]);
        }

        // write h (hi/lo bf16) to pong buffer + layer output
        bf16 h0h, h0l, h1h, h1l, h2h, h2l, h3h, h3l;
        split_bf(hn[0], h0h, h0l); split_bf(hn[1], h1h, h1l);
        split_bf(hn[2], h2h, h2l); split_bf(hn[3], h3h, h3l);
        unsigned p0h = pack2(h0h, h1h), p0l = pack2(h0l, h1l);
        unsigned p1h = pack2(h2h, h3h), p1l = pack2(h2l, h3l);
        size_t hb = ((size_t)(d * 2 + ((t + 1) & 1)) * BB + m1) * HH + j0 + u0;
        *(unsigned*)&d_hbh[hb] = p0h;
        *(unsigned*)&d_hbl[hb] = p0l;
        *(unsigned*)&d_hbh[hb + (size_t)8 * HH] = p1h;
        *(unsigned*)&d_hbl[hb + (size_t)8 * HH] = p1l;

        if (PH == 0) {
            size_t xo1 = ((size_t)m1 * SS + tt) * HDI + d * HH + j0 + u0;
            *(unsigned*)&d_x1h[xo1] = p0h;
            *(unsigned*)&d_x1l[xo1] = p0l;
            size_t xo2 = ((size_t)(m1 + 8) * SS + tt) * HDI + d * HH + j0 + u0;
            *(unsigned*)&d_x1h[xo2] = p1h;
            *(unsigned*)&d_x1l[xo2] = p1l;
        } else {
            float2 v0; v0.x = hn[0]; v0.y = hn[1];
            float2 v1; v1.x = hn[2]; v1.y = hn[3];
            *(float2*)&d_x2[((size_t)m1 * SS + tt) * HDI + d * HH + j0 + u0] = v0;
            *(float2*)&d_x2[((size_t)(m1 + 8) * SS + tt) * HDI + d * HH + j0 + u0] = v1;
        }

        grid_barrier_d(d, blk);
    }
}

// ---------------- classifier ----------------
__global__ void k_logits(const float* __restrict__ clsw, const float* __restrict__ clsb) {
    int gwarp = (blockIdx.x * blockDim.x + threadIdx.x) >> 5;
    int lane = threadIdx.x & 31;
    if (gwarp >= BB * SS) return;
    const float4* xr = (const float4*)(d_x2 + (size_t)gwarp * HDI);
    float4 xv[8];
#pragma unroll
    for (int q = 0; q < 8; q++) xv[q] = xr[lane + 32 * q];
#pragma unroll
    for (int t = 0; t < TT; t++) {
        const float4* wr = (const float4*)(clsw + (size_t)t * HDI);
        float p = 0.f;
#pragma unroll
        for (int q = 0; q < 8; q++) {
            float4 wv = wr[lane + 32 * q];
            p += xv[q].x * wv.x + xv[q].y * wv.y + xv[q].z * wv.z + xv[q].w * wv.w;
        }
#pragma unroll
        for (int o = 16; o > 0; o >>= 1) p += __shfl_down_sync(0xffffffffu, p, o);
        if (lane == 0) d_logits[(size_t)gwarp * TT + t] = p + clsb[t];
    }
}

// ---------------- CRF ----------------
__global__ void k_crf(const int* __restrict__ labels, const int* __restrict__ vlens,
                      const float* __restrict__ trans, const float* __restrict__ startt,
                      const float* __restrict__ endt, float* __restrict__ out) {
    __shared__ float tr[TT * TT];
    __shared__ float alpha[TT], score[TT];
    __shared__ unsigned char hist[SS][TT];
    __shared__ float logZ_s;
    __shared__ int blast_s;

    const int b = blockIdx.x;
    const int tid = threadIdx.x;
    const int vl = vlens[b];
    const float* lg = d_logits + (size_t)b * SS * TT;
    const int* lab = labels + (size_t)b * SS;

    for (int i = tid; i < TT * TT; i += 32) tr[i] = trans[i];
    if (tid < TT) {
        float e = lg[tid];
        alpha[tid] = startt[tid] + e;
        score[tid] = startt[tid] + e;
    }
    __syncwarp();

    for (int t = 1; t < SS; t++) {
        float ns = 0.f, na = 0.f;
        int barg = 0;
        if (tid < TT) {
            float em = lg[t * TT + tid];
            float best = -1e30f, mx = -1e30f;
#pragma unroll
            for (int i = 0; i < TT; i++) {
                float v = score[i] + tr[i * TT + tid];
                if (v > best) { best = v; barg = i; }
                float a = alpha[i] + tr[i * TT + tid];
                mx = fmaxf(mx, a);
            }
            float ssum = 0.f;
#pragma unroll
            for (int i = 0; i < TT; i++) ssum += expf(alpha[i] + tr[i * TT + tid] - mx);
            ns = best + em;
            na = mx + logf(ssum) + em;
            hist[t][tid] = (unsigned char)barg;
        }
        __syncwarp();
        if (tid < TT && t < vl) { score[tid] = ns; alpha[tid] = na; }
        __syncwarp();
    }

    if (tid == 0) {
        float best = -1e30f, mx = -1e30f;
        int ba = 0;
        for (int j = 0; j < TT; j++) {
            float v = score[j] + endt[j];
            if (v > best) { best = v; ba = j; }
            mx = fmaxf(mx, alpha[j] + endt[j]);
        }
        float ss = 0.f;
        for (int j = 0; j < TT; j++) ss += expf(alpha[j] + endt[j] - mx);
        logZ_s = mx + logf(ss);
        blast_s = ba;
    }

    float np = 0.f;
    for (int t = 1 + tid; t < SS; t += 32) {
        if (t < vl) np += lg[t * TT + lab[t]] + tr[lab[t - 1] * TT + lab[t]];
    }
#pragma unroll
    for (int o = 16; o > 0; o >>= 1) np += __shfl_down_sync(0xffffffffu, np, o);
    __syncwarp();

    if (tid == 0) {
        float num = startt[lab[0]] + lg[lab[0]] + np + endt[lab[vl - 1]];
        d_llh[b] = num - logZ_s;
        int tag = blast_s;
        out[(size_t)b * SS + SS - 1] = (float)tag;
        for (int t = SS - 1; t >= 1; t--) {
            if (t < vl) tag = hist[t][tag];
            out[(size_t)b * SS + t - 1] = (float)tag;
        }
    }
}

__global__ void k_loss(float* __restrict__ out) {
    __shared__ float s[BB];
    s[threadIdx.x] = d_llh[threadIdx.x];
    __syncthreads();
    if (threadIdx.x == 0) {
        float t = 0.f;
        for (int i = 0; i < BB; i++) t += s[i];
        out[BB * SS] = -t / (float)BB;
    }
}

// ---------------- launch ----------------
extern "C" void kernel_launch(void* const* d_in, const int* in_sizes, int n_in,
                              void* d_out, int out_size) {
    const int*   ids    = (const int*)d_in[0];
    const int*   vlens  = (const int*)d_in[1];
    const int*   labels = (const int*)d_in[2];
    const float* emb    = (const float*)d_in[3];
    const float* w_ih0  = (const float*)d_in[4];
    const float* w_hh0  = (const float*)d_in[5];
    const float* b_ih0  = (const float*)d_in[6];
    const float* b_hh0  = (const float*)d_in[7];
    const float* w_ih1  = (const float*)d_in[8];
    const float* w_hh1  = (const float*)d_in[9];
    const float* b_ih1  = (const float*)d_in[10];
    const float* b_hh1  = (const float*)d_in[11];
    const float* cls_w  = (const float*)d_in[12];
    const float* cls_b  = (const float*)d_in[13];
    const float* trans  = (const float*)d_in[14];
    const float* start_t = (const float*)d_in[15];
    const float* end_t   = (const float*)d_in[16];
    float* out = (float*)d_out;

    const int GEMM_SMEM = 3 * GSTAGE * 2;                          // 184320 B
    const int SCAN_SMEM = (2 * WS_ELEMS + 3 * 2 * CH_ELEMS) * 2;   // 171008 B
    cudaFuncSetAttribute(k_gemm<0>, cudaFuncAttributeMaxDynamicSharedMemorySize, GEMM_SMEM);
    cudaFuncSetAttribute(k_gemm<1>, cudaFuncAttributeMaxDynamicSharedMemorySize, GEMM_SMEM);
    cudaFuncSetAttribute(k_scan<0>, cudaFuncAttributeMaxDynamicSharedMemorySize, SCAN_SMEM);
    cudaFuncSetAttribute(k_scan<1>, cudaFuncAttributeMaxDynamicSharedMemorySize, SCAN_SMEM);

    bf16 *w0h, *w0l, *w1h, *w1l;
    cudaGetSymbolAddress((void**)&w0h, d_w0h);
    cudaGetSymbolAddress((void**)&w0l, d_w0l);
    cudaGetSymbolAddress((void**)&w1h, d_w1h);
    cudaGetSymbolAddress((void**)&w1l, d_w1l);

    // prep: embedding + weight splits
    k_embed<<<BB * SS, 64>>>(ids, emb);
    k_split<<<(NG * EE + 255) / 256, 256>>>(w_ih0, w0h, w0l, NG * EE);
    k_split<<<(NG * HDI + 255) / 256, 256>>>(w_ih1, w1h, w1l, NG * HDI);

    dim3 ggrid(NG / 256, MR / 128);
    // layer 0
    k_gemm<0><<<ggrid, 512, GEMM_SMEM>>>(b_ih0, b_hh0);
    k_scan<0><<<128, 128, SCAN_SMEM>>>(w_hh0, 64);
    // layer 1
    k_gemm<1><<<ggrid, 512, GEMM_SMEM>>>(b_ih1, b_hh1);
    k_scan<1><<<128, 128, SCAN_SMEM>>>(w_hh1, 64);
    // classifier + CRF
    k_logits<<<(BB * SS) / 8, 256>>>(cls_w, cls_b);
    k_crf<<<BB, 32>>>(labels, vlens, trans, start_t, end_t, out);
    k_loss<<<1, BB>>>(out);
}

// round 14
// speedup vs baseline: 1.1478x; 1.1478x over previous
#include <cuda_runtime.h>
#include <cuda_bf16.h>
#include <cstdint>
#include <math.h>

#define BB 64
#define SS 512
#define EE 256
#define HH 512
#define HDI 1024
#define G4 2048              // 4*H
#define NG 4096              // 2 dirs * 4H
#define TT 9
#define MR (BB*SS)           // 32768 rows

typedef __nv_bfloat16 bf16;

// ---------------- static device buffers ----------------
__device__ __align__(256) bf16  d_x0h[(size_t)MR * EE];
__device__ __align__(256) bf16  d_x0l[(size_t)MR * EE];
__device__ __align__(256) bf16  d_w0h[(size_t)NG * EE];
__device__ __align__(256) bf16  d_w0l[(size_t)NG * EE];
__device__ __align__(256) bf16  d_w1h[(size_t)NG * HDI];
__device__ __align__(256) bf16  d_w1l[(size_t)NG * HDI];
__device__ __align__(256) float d_xg0[(size_t)2 * SS * BB * G4];
__device__ __align__(256) float d_xg1[(size_t)2 * SS * BB * G4];
__device__ __align__(256) bf16  d_x1h[(size_t)MR * HDI];
__device__ __align__(256) bf16  d_x1l[(size_t)MR * HDI];
__device__ __align__(256) float d_x2[(size_t)MR * HDI];
__device__ __align__(256) bf16  d_hbh[2 * 2 * BB * HH];    // [dir][pp][m][k]
__device__ __align__(256) bf16  d_hbl[2 * 2 * BB * HH];
__device__ __align__(256) float d_logits[(size_t)MR * TT];
__device__ float d_llh[BB];
__device__ unsigned g_cnt2[2 * 32];                         // per-dir barrier (padded)
__device__ unsigned g_gen2[2 * 32];

// ---------------- helpers ----------------
__device__ __forceinline__ void split_bf(float x, bf16 &h, bf16 &l) {
    h = __float2bfloat16(x);
    l = __float2bfloat16(x - __bfloat162float(h));
}
__device__ __forceinline__ unsigned pack2(bf16 a, bf16 b) {
    __nv_bfloat162 v; v.x = a; v.y = b;
    return *(unsigned*)&v;
}
__device__ __forceinline__ void mma_bf16(float* c, unsigned a0, unsigned a1,
                                         unsigned a2, unsigned a3,
                                         unsigned b0, unsigned b1) {
    asm volatile(
        "mma.sync.aligned.m16n8k16.row.col.f32.bf16.bf16.f32 "
        "{%0,%1,%2,%3}, {%4,%5,%6,%7}, {%8,%9}, {%0,%1,%2,%3};"
        : "+f"(c[0]), "+f"(c[1]), "+f"(c[2]), "+f"(c[3])
        : "r"(a0), "r"(a1), "r"(a2), "r"(a3), "r"(b0), "r"(b1));
}
#define LDSM4(r0, r1, r2, r3, addr) \
    asm volatile("ldmatrix.sync.aligned.m8n8.x4.shared.b16 {%0,%1,%2,%3}, [%4];" \
        : "=r"(r0), "=r"(r1), "=r"(r2), "=r"(r3) : "r"(addr))
#define CPA16(dst_u32, src) \
    asm volatile("cp.async.cg.shared.global [%0], [%1], 16;" :: "r"(dst_u32), "l"(src))
#define CP_COMMIT() asm volatile("cp.async.commit_group;")
#define CP_WAIT1()  asm volatile("cp.async.wait_group 1;")
#define CP_WAIT0()  asm volatile("cp.async.wait_group 0;")

// ---------------- per-direction grid barrier (flat atomic-polling; best known) ----------------
__device__ __forceinline__ void grid_barrier_d(int d, int nb) {
    __syncthreads();
    if (threadIdx.x == 0) {
        unsigned* cnt = &g_cnt2[d * 32];
        unsigned* gen = &g_gen2[d * 32];
        __threadfence();
        unsigned g = atomicAdd(gen, 0u);
        unsigned r = atomicAdd(cnt, 1u);
        if (r == (unsigned)nb - 1u) {
            atomicExch(cnt, 0u);
            __threadfence();
            atomicAdd(gen, 1u);
        } else {
            while (atomicAdd(gen, 0u) == g) { __nanosleep(64); }
        }
        __threadfence();
    }
    __syncthreads();
}

// ---------------- embedding gather + bf16 split ----------------
__global__ void k_embed(const int* __restrict__ ids, const float* __restrict__ emb) {
    int row = blockIdx.x;
    int tid = threadIdx.x;                    // 64 threads, 4 cols each
    const float4* src = (const float4*)(emb + (size_t)ids[row] * EE);
    float4 v = src[tid];
    bf16 h0, l0, h1, l1, h2, l2, h3, l3;
    split_bf(v.x, h0, l0); split_bf(v.y, h1, l1);
    split_bf(v.z, h2, l2); split_bf(v.w, h3, l3);
    size_t o = (size_t)row * EE + 4 * tid;
    *(unsigned*)&d_x0h[o]     = pack2(h0, h1);
    *(unsigned*)&d_x0h[o + 2] = pack2(h2, h3);
    *(unsigned*)&d_x0l[o]     = pack2(l0, l1);
    *(unsigned*)&d_x0l[o + 2] = pack2(l2, l3);
}

// ---------------- weight split ----------------
__global__ void k_split(const float* __restrict__ src, bf16* __restrict__ h,
                        bf16* __restrict__ l, int n) {
    int i = blockIdx.x * blockDim.x + threadIdx.x;
    if (i < n) { bf16 a, b; split_bf(src[i], a, b); h[i] = a; l[i] = b; }
}

// ---------------- input-projection GEMM (3xBF16 mma + ldmatrix, 128x256 tile) ----------------
// Block 128(m) x 256(n), Kt=32, 16 warps (2x8), warp tile 64x32.
// Stage layout (rows x GST): Ah[128] Al[128] Wh[256] Wl[256] = 768 rows.
#define GST 40                                   // smem row stride (bf16 elems)
#define GSTAGE (768 * GST)                       // elems per stage
template <int PH>
__global__ void __launch_bounds__(512) k_gemm(const float* __restrict__ bih,
                                              const float* __restrict__ bhh) {
    constexpr int K = (PH == 0) ? EE : HDI;
    const bf16* Ah = (PH == 0) ? d_x0h : d_x1h;
    const bf16* Al = (PH == 0) ? d_x0l : d_x1l;
    const bf16* Wh = (PH == 0) ? d_w0h : d_w1h;
    const bf16* Wl = (PH == 0) ? d_w0l : d_w1l;
    float* xg      = (PH == 0) ? d_xg0 : d_xg1;

    extern __shared__ bf16 sm[];
    const unsigned sm_u32 = (unsigned)__cvta_generic_to_shared(sm);

    const int m0 = blockIdx.y * 128;
    const int n0 = blockIdx.x * 256;
    const int tid = threadIdx.x;
    const int wid = tid >> 5;
    const int lane = tid & 31;
    const int wm = (wid >> 3) * 64;              // 2 m-groups of 64
    const int wn = (wid & 7) * 32;               // 8 n-tiles of 32

    // ldmatrix lane offsets (bytes)
    const unsigned laneA = (((lane & 7) + ((lane >> 3) & 1) * 8) * GST + (lane >> 4) * 8) * 2;
    const unsigned laneB = (((lane & 7) + (lane >> 4) * 8) * GST + ((lane >> 3) & 1) * 8) * 2;

    float acc[4][4][4];
#pragma unroll
    for (int i = 0; i < 4; i++)
#pragma unroll
        for (int j = 0; j < 4; j++)
#pragma unroll
            for (int q = 0; q < 4; q++) acc[i][j][q] = 0.f;

    const bf16* gsrc[4] = {Ah, Al, Wh, Wl};
    const int rowbase[4] = {m0, m0, n0, n0};
    const int arrbase[4] = {0, 128 * GST, 256 * GST, 512 * GST};

    auto stage = [&](int s, int k0) {
#pragma unroll
        for (int i = 0; i < 6; i++) {
            int slot = tid + 512 * i;            // 0..3071
            int gr = slot >> 2;                  // 0..767
            int seg = slot & 3;
            int q = gr >> 7;                     // 0..5
            int arr = (q < 2) ? q : (q < 4) ? 2 : 3;
            int row = (q < 2) ? (gr & 127) : (gr & 255);
            const bf16* src = gsrc[arr] + (size_t)(rowbase[arr] + row) * K + k0 + seg * 8;
            unsigned dst = sm_u32 + (unsigned)((s * GSTAGE + arrbase[arr] + row * GST + seg * 8) * 2);
            CPA16(dst, src);
        }
        CP_COMMIT();
    };

    constexpr int KT = K / 32;
    stage(0, 0);
    stage(1, 32);
    for (int it = 0; it < KT; it++) {
        if (it + 1 < KT) { CP_WAIT1(); } else { CP_WAIT0(); }
        __syncthreads();
        if (it + 2 < KT) stage((it + 2) % 3, (it + 2) * 32);

        const unsigned sbase = sm_u32 + (unsigned)((it % 3) * GSTAGE * 2);
        const unsigned aAh = sbase + (unsigned)(wm * GST * 2) + laneA;
        const unsigned aAl = aAh + (unsigned)(128 * GST * 2);
        const unsigned aWh = sbase + (unsigned)(256 * GST * 2) + (unsigned)(wn * GST * 2) + laneB;
        const unsigned aWl = aWh + (unsigned)(256 * GST * 2);

#pragma unroll
        for (int kk = 0; kk < 32; kk += 16) {
            unsigned ah[4][4], al[4][4], bh[2][4], bl[2][4];
#pragma unroll
            for (int mi = 0; mi < 4; mi++) {
                unsigned off = (unsigned)(mi * 16 * GST * 2 + kk * 2);
                LDSM4(ah[mi][0], ah[mi][1], ah[mi][2], ah[mi][3], aAh + off);
                LDSM4(al[mi][0], al[mi][1], al[mi][2], al[mi][3], aAl + off);
            }
#pragma unroll
            for (int np = 0; np < 2; np++) {
                unsigned off = (unsigned)(np * 16 * GST * 2 + kk * 2);
                LDSM4(bh[np][0], bh[np][1], bh[np][2], bh[np][3], aWh + off);
                LDSM4(bl[np][0], bl[np][1], bl[np][2], bl[np][3], aWl + off);
            }
#pragma unroll
            for (int np = 0; np < 2; np++)
#pragma unroll
                for (int j = 0; j < 2; j++) {
                    int ni = np * 2 + j;
                    unsigned b0h = bh[np][2 * j], b1h = bh[np][2 * j + 1];
                    unsigned b0l = bl[np][2 * j], b1l = bl[np][2 * j + 1];
#pragma unroll
                    for (int mi = 0; mi < 4; mi++) {
                        mma_bf16(acc[mi][ni], ah[mi][0], ah[mi][1], ah[mi][2], ah[mi][3], b0h, b1h);
                        mma_bf16(acc[mi][ni], ah[mi][0], ah[mi][1], ah[mi][2], ah[mi][3], b0l, b1l);
                        mma_bf16(acc[mi][ni], al[mi][0], al[mi][1], al[mi][2], al[mi][3], b0h, b1h);
                    }
                }
        }
    }

    // epilogue: bias + scatter to xg[d][s][b][gate]
    const int fr2 = lane >> 2;
    const int fc2 = lane & 3;
#pragma unroll
    for (int ni = 0; ni < 4; ni++) {
        int ncol = n0 + wn + ni * 8 + 2 * fc2;
        float bias0 = bih[ncol] + bhh[ncol];
        float bias1 = bih[ncol + 1] + bhh[ncol + 1];
        int d = ncol >> 11;
        int gate = ncol & 2047;
#pragma unroll
        for (int mi = 0; mi < 4; mi++) {
#pragma unroll
            for (int half = 0; half < 2; half++) {
                int m = m0 + wm + mi * 16 + fr2 + half * 8;
                int b = m >> 9;
                int s = m & 511;
                float2 v;
                v.x = acc[mi][ni][half * 2 + 0] + bias0;
                v.y = acc[mi][ni][half * 2 + 1] + bias1;
                *(float2*)(xg + ((size_t)(d * SS + s) * BB + b) * G4 + gate) = v;
            }
        }
    }
}

// ---------------- persistent bidirectional LSTM scan (warp-private staging) ----------------
// 128 blocks: (dir, 8 hidden units). 128 threads (4 warps).
// Per step: G[64b][32c] = h[64][512] @ Wslice^T via m16n8k16, gates in-register.
// 4 chunks of k=128 in 3 rotating smem slots. Each warp stages ONLY its own 16
// chunk rows -> chunk visibility is intra-warp (wait_group + syncwarp); zero
// block-wide syncs inside the chunk loop.
#define WST 520                                  // ws row stride
#define CST 136                                  // chunk row stride (128 + 8 pad)
#define WS_ELEMS (32 * WST)
#define CH_ELEMS (64 * CST)
template <int PH>
__global__ void __launch_bounds__(128, 1) k_scan(const float* __restrict__ whh, int nb) {
    extern __shared__ bf16 sm[];
    bf16* wsh = sm;                              // [32][WST]  c = g*8 + jj ordering
    bf16* wsl = sm + WS_ELEMS;
    const unsigned ws_u32 = (unsigned)__cvta_generic_to_shared(sm);
    const unsigned chk_u32 = ws_u32 + (unsigned)(2 * WS_ELEMS * 2);

    const float* xg = (PH == 0) ? d_xg0 : d_xg1;

    const int tid = threadIdx.x;
    const int d = blockIdx.x >> 6;
    const int j0 = (blockIdx.x & 63) * 8;

    // preload recurrent weight slice: ws[c][k], c = g*8 + jj
    for (int idx = tid; idx < 32 * HH; idx += 128) {
        int c = idx >> 9;
        int k = idx & 511;
        int g = c >> 3, jj = c & 7;
        float w = whh[((size_t)d * G4 + (size_t)g * HH + j0 + jj) * HH + k];
        bf16 h, l; split_bf(w, h, l);
        wsh[c * WST + k] = h;
        wsl[c * WST + k] = l;
    }
    // zero ping h (pp=0) for this block's 8 columns
    for (int idx = tid; idx < 64 * 4; idx += 128) {
        int m = idx >> 2, q = idx & 3;
        *(unsigned*)&d_hbh[((size_t)(d * 2 + 0) * BB + m) * HH + j0 + 2 * q] = 0u;
        *(unsigned*)&d_hbl[((size_t)(d * 2 + 0) * BB + m) * HH + j0 + 2 * q] = 0u;
    }
    grid_barrier_d(d, nb);

    const int lane = tid & 31;
    const int w = tid >> 5;
    const int fr = lane >> 2;
    const int fc = lane & 3;
    const int m1 = w * 16 + fr;                  // rows m1, m1+8
    const int u0 = 2 * fc;                       // units u0, u0+1

    // ldmatrix lane offsets (bytes)
    const unsigned laneA = (((lane & 7) + ((lane >> 3) & 1) * 8) * CST + (lane >> 4) * 8) * 2;
    const unsigned laneB = (((lane & 7) + (lane >> 4) * 8) * WST + ((lane >> 3) & 1) * 8) * 2;
    const unsigned aAbase = chk_u32 + (unsigned)(w * 16 * CST * 2) + laneA;

    float creg[4] = {0.f, 0.f, 0.f, 0.f};

    for (int t = 0; t < SS; t++) {
        const int tt = d ? (SS - 1 - t) : t;
        const bf16* hsh = d_hbh + ((size_t)(d * 2 + (t & 1)) * BB) * HH;
        const bf16* hsl = d_hbl + ((size_t)(d * 2 + (t & 1)) * BB) * HH;

        // warp-private stage: warp w copies ONLY rows [w*16, w*16+16) of chunk c
        // into slot s (hi + lo): 512 copies per warp, 16 per lane.
        auto stg = [&](int s, int c) {
            int k0 = c * 128;
            unsigned sb = chk_u32 + (unsigned)(s * 2 * CH_ELEMS * 2);
#pragma unroll
            for (int i = 0; i < 16; i++) {
                int slot = lane + 32 * i;        // 0..511 (warp's own work)
                int arr = slot >> 8;             // 0: hi, 1: lo
                int wi = slot & 255;
                int row16 = wi >> 4;             // 0..15
                int seg = wi & 15;               // k = k0 + seg*8
                int row = w * 16 + row16;
                const bf16* src = (arr ? hsl : hsh) + (size_t)row * HH + k0 + seg * 8;
                unsigned dst = sb + (unsigned)((arr * CH_ELEMS + row * CST + seg * 8) * 2);
                CPA16(dst, src);
            }
            CP_COMMIT();
        };
        stg(0, 0);
        stg(1, 1);

        // prefetch xg (independent of h)
        const float* xb = xg + (((size_t)d * SS + tt) * BB + m1) * G4 + j0 + u0;
        float2 xv[8];
#pragma unroll
        for (int g = 0; g < 4; g++) {
            xv[g * 2 + 0] = *(const float2*)(xb + (size_t)g * HH);
            xv[g * 2 + 1] = *(const float2*)(xb + (size_t)g * HH + (size_t)8 * G4);
        }

        float acc[4][4];
#pragma unroll
        for (int g = 0; g < 4; g++)
#pragma unroll
            for (int q = 0; q < 4; q++) acc[g][q] = 0.f;

        for (int c = 0; c < 4; c++) {
            if (c < 3) { CP_WAIT1(); } else { CP_WAIT0(); }
            __syncwarp();
            if (c + 2 < 4) stg((c + 2) % 3, c + 2);

            const unsigned aA = aAbase + (unsigned)((c % 3) * 2 * CH_ELEMS * 2);
            const unsigned aWb = ws_u32 + (unsigned)(c * 128 * 2) + laneB;
#pragma unroll
            for (int kk = 0; kk < 128; kk += 16) {
                unsigned a0, a1, a2, a3, c0, c1, c2, c3;
                LDSM4(a0, a1, a2, a3, aA + (unsigned)(kk * 2));
                LDSM4(c0, c1, c2, c3, aA + (unsigned)(CH_ELEMS * 2 + kk * 2));
#pragma unroll
                for (int np = 0; np < 2; np++) {
                    unsigned bh0, bh1, bh2, bh3, bl0, bl1, bl2, bl3;
                    unsigned off = (unsigned)(np * 16 * WST * 2 + kk * 2);
                    LDSM4(bh0, bh1, bh2, bh3, aWb + off);
                    LDSM4(bl0, bl1, bl2, bl3, aWb + (unsigned)(WS_ELEMS * 2) + off);
                    int n0i = np * 2;
                    mma_bf16(acc[n0i], a0, a1, a2, a3, bh0, bh1);
                    mma_bf16(acc[n0i], a0, a1, a2, a3, bl0, bl1);
                    mma_bf16(acc[n0i], c0, c1, c2, c3, bh0, bh1);
                    mma_bf16(acc[n0i + 1], a0, a1, a2, a3, bh2, bh3);
                    mma_bf16(acc[n0i + 1], a0, a1, a2, a3, bl2, bl3);
                    mma_bf16(acc[n0i + 1], c0, c1, c2, c3, bh2, bh3);
                }
            }
        }

        // gates: cell q -> (row m1 + 8*(q>>1), unit u0 + (q&1)), acc[g][q]
        float hn[4];
#pragma unroll
        for (int q = 0; q < 4; q++) {
            int rh = q >> 1;
            float xi = (q & 1) ? xv[0 + rh].y : xv[0 + rh].x;
            float xf = (q & 1) ? xv[2 + rh].y : xv[2 + rh].x;
            float xgv = (q & 1) ? xv[4 + rh].y : xv[4 + rh].x;
            float xo = (q & 1) ? xv[6 + rh].y : xv[6 + rh].x;
            float vi = acc[0][q] + xi;
            float vf = acc[1][q] + xf;
            float vg = acc[2][q] + xgv;
            float vo = acc[3][q] + xo;
            float si = 1.f / (1.f + expf(-vi));
            float sf = 1.f / (1.f + expf(-vf));
            float so = 1.f / (1.f + expf(-vo));
            float tg = tanhf(vg);
            creg[q] = sf * creg[q] + si * tg;
            hn[q] = so * tanhf(creg[q]);
        }

        // write h (hi/lo bf16) to pong buffer + layer output
        bf16 h0h, h0l, h1h, h1l, h2h, h2l, h3h, h3l;
        split_bf(hn[0], h0h, h0l); split_bf(hn[1], h1h, h1l);
        split_bf(hn[2], h2h, h2l); split_bf(hn[3], h3h, h3l);
        unsigned p0h = pack2(h0h, h1h), p0l = pack2(h0l, h1l);
        unsigned p1h = pack2(h2h, h3h), p1l = pack2(h2l, h3l);
        size_t hb = ((size_t)(d * 2 + ((t + 1) & 1)) * BB + m1) * HH + j0 + u0;
        *(unsigned*)&d_hbh[hb] = p0h;
        *(unsigned*)&d_hbl[hb] = p0l;
        *(unsigned*)&d_hbh[hb + (size_t)8 * HH] = p1h;
        *(unsigned*)&d_hbl[hb + (size_t)8 * HH] = p1l;

        if (PH == 0) {
            size_t xo1 = ((size_t)m1 * SS + tt) * HDI + d * HH + j0 + u0;
            *(unsigned*)&d_x1h[xo1] = p0h;
            *(unsigned*)&d_x1l[xo1] = p0l;
            size_t xo2 = ((size_t)(m1 + 8) * SS + tt) * HDI + d * HH + j0 + u0;
            *(unsigned*)&d_x1h[xo2] = p1h;
            *(unsigned*)&d_x1l[xo2] = p1l;
        } else {
            float2 v0; v0.x = hn[0]; v0.y = hn[1];
            float2 v1; v1.x = hn[2]; v1.y = hn[3];
            *(float2*)&d_x2[((size_t)m1 * SS + tt) * HDI + d * HH + j0 + u0] = v0;
            *(float2*)&d_x2[((size_t)(m1 + 8) * SS + tt) * HDI + d * HH + j0 + u0] = v1;
        }

        grid_barrier_d(d, nb);
    }
}

// ---------------- classifier ----------------
__global__ void k_logits(const float* __restrict__ clsw, const float* __restrict__ clsb) {
    int gwarp = (blockIdx.x * blockDim.x + threadIdx.x) >> 5;
    int lane = threadIdx.x & 31;
    if (gwarp >= BB * SS) return;
    const float4* xr = (const float4*)(d_x2 + (size_t)gwarp * HDI);
    float4 xv[8];
#pragma unroll
    for (int q = 0; q < 8; q++) xv[q] = xr[lane + 32 * q];
#pragma unroll
    for (int t = 0; t < TT; t++) {
        const float4* wr = (const float4*)(clsw + (size_t)t * HDI);
        float p = 0.f;
#pragma unroll
        for (int q = 0; q < 8; q++) {
            float4 wv = wr[lane + 32 * q];
            p += xv[q].x * wv.x + xv[q].y * wv.y + xv[q].z * wv.z + xv[q].w * wv.w;
        }
#pragma unroll
        for (int o = 16; o > 0; o >>= 1) p += __shfl_down_sync(0xffffffffu, p, o);
        if (lane == 0) d_logits[(size_t)gwarp * TT + t] = p + clsb[t];
    }
}

// ---------------- CRF ----------------
__global__ void k_crf(const int* __restrict__ labels, const int* __restrict__ vlens,
                      const float* __restrict__ trans, const float* __restrict__ startt,
                      const float* __restrict__ endt, float* __restrict__ out) {
    __shared__ float tr[TT * TT];
    __shared__ float alpha[TT], score[TT];
    __shared__ unsigned char hist[SS][TT];
    __shared__ float logZ_s;
    __shared__ int blast_s;

    const int b = blockIdx.x;
    const int tid = threadIdx.x;
    const int vl = vlens[b];
    const float* lg = d_logits + (size_t)b * SS * TT;
    const int* lab = labels + (size_t)b * SS;

    for (int i = tid; i < TT * TT; i += 32) tr[i] = trans[i];
    if (tid < TT) {
        float e = lg[tid];
        alpha[tid] = startt[tid] + e;
        score[tid] = startt[tid] + e;
    }
    __syncwarp();

    for (int t = 1; t < SS; t++) {
        float ns = 0.f, na = 0.f;
        int barg = 0;
        if (tid < TT) {
            float em = lg[t * TT + tid];
            float best = -1e30f, mx = -1e30f;
#pragma unroll
            for (int i = 0; i < TT; i++) {
                float v = score[i] + tr[i * TT + tid];
                if (v > best) { best = v; barg = i; }
                float a = alpha[i] + tr[i * TT + tid];
                mx = fmaxf(mx, a);
            }
            float ssum = 0.f;
#pragma unroll
            for (int i = 0; i < TT; i++) ssum += expf(alpha[i] + tr[i * TT + tid] - mx);
            ns = best + em;
            na = mx + logf(ssum) + em;
            hist[t][tid] = (unsigned char)barg;
        }
        __syncwarp();
        if (tid < TT && t < vl) { score[tid] = ns; alpha[tid] = na; }
        __syncwarp();
    }

    if (tid == 0) {
        float best = -1e30f, mx = -1e30f;
        int ba = 0;
        for (int j = 0; j < TT; j++) {
            float v = score[j] + endt[j];
            if (v > best) { best = v; ba = j; }
            mx = fmaxf(mx, alpha[j] + endt[j]);
        }
        float ss = 0.f;
        for (int j = 0; j < TT; j++) ss += expf(alpha[j] + endt[j] - mx);
        logZ_s = mx + logf(ss);
        blast_s = ba;
    }

    float np = 0.f;
    for (int t = 1 + tid; t < SS; t += 32) {
        if (t < vl) np += lg[t * TT + lab[t]] + tr[lab[t - 1] * TT + lab[t]];
    }
#pragma unroll
    for (int o = 16; o > 0; o >>= 1) np += __shfl_down_sync(0xffffffffu, np, o);
    __syncwarp();

    if (tid == 0) {
        float num = startt[lab[0]] + lg[lab[0]] + np + endt[lab[vl - 1]];
        d_llh[b] = num - logZ_s;
        int tag = blast_s;
        out[(size_t)b * SS + SS - 1] = (float)tag;
        for (int t = SS - 1; t >= 1; t--) {
            if (t < vl) tag = hist[t][tag];
            out[(size_t)b * SS + t - 1] = (float)tag;
        }
    }
}

__global__ void k_loss(float* __restrict__ out) {
    __shared__ float s[BB];
    s[threadIdx.x] = d_llh[threadIdx.x];
    __syncthreads();
    if (threadIdx.x == 0) {
        float t = 0.f;
        for (int i = 0; i < BB; i++) t += s[i];
        out[BB * SS] = -t / (float)BB;
    }
}

// ---------------- launch ----------------
extern "C" void kernel_launch(void* const* d_in, const int* in_sizes, int n_in,
                              void* d_out, int out_size) {
    const int*   ids    = (const int*)d_in[0];
    const int*   vlens  = (const int*)d_in[1];
    const int*   labels = (const int*)d_in[2];
    const float* emb    = (const float*)d_in[3];
    const float* w_ih0  = (const float*)d_in[4];
    const float* w_hh0  = (const float*)d_in[5];
    const float* b_ih0  = (const float*)d_in[6];
    const float* b_hh0  = (const float*)d_in[7];
    const float* w_ih1  = (const float*)d_in[8];
    const float* w_hh1  = (const float*)d_in[9];
    const float* b_ih1  = (const float*)d_in[10];
    const float* b_hh1  = (const float*)d_in[11];
    const float* cls_w  = (const float*)d_in[12];
    const float* cls_b  = (const float*)d_in[13];
    const float* trans  = (const float*)d_in[14];
    const float* start_t = (const float*)d_in[15];
    const float* end_t   = (const float*)d_in[16];
    float* out = (float*)d_out;

    const int GEMM_SMEM = 3 * GSTAGE * 2;                          // 184320 B
    const int SCAN_SMEM = (2 * WS_ELEMS + 3 * 2 * CH_ELEMS) * 2;   // 171008 B
    cudaFuncSetAttribute(k_gemm<0>, cudaFuncAttributeMaxDynamicSharedMemorySize, GEMM_SMEM);
    cudaFuncSetAttribute(k_gemm<1>, cudaFuncAttributeMaxDynamicSharedMemorySize, GEMM_SMEM);
    cudaFuncSetAttribute(k_scan<0>, cudaFuncAttributeMaxDynamicSharedMemorySize, SCAN_SMEM);
    cudaFuncSetAttribute(k_scan<1>, cudaFuncAttributeMaxDynamicSharedMemorySize, SCAN_SMEM);

    bf16 *w0h, *w0l, *w1h, *w1l;
    cudaGetSymbolAddress((void**)&w0h, d_w0h);
    cudaGetSymbolAddress((void**)&w0l, d_w0l);
    cudaGetSymbolAddress((void**)&w1h, d_w1h);
    cudaGetSymbolAddress((void**)&w1l, d_w1l);

    // prep: embedding + weight splits
    k_embed<<<BB * SS, 64>>>(ids, emb);
    k_split<<<(NG * EE + 255) / 256, 256>>>(w_ih0, w0h, w0l, NG * EE);
    k_split<<<(NG * HDI + 255) / 256, 256>>>(w_ih1, w1h, w1l, NG * HDI);

    dim3 ggrid(NG / 256, MR / 128);
    // layer 0
    k_gemm<0><<<ggrid, 512, GEMM_SMEM>>>(b_ih0, b_hh0);
    k_scan<0><<<128, 128, SCAN_SMEM>>>(w_hh0, 64);
    // layer 1
    k_gemm<1><<<ggrid, 512, GEMM_SMEM>>>(b_ih1, b_hh1);
    k_scan<1><<<128, 128, SCAN_SMEM>>>(w_hh1, 64);
    // classifier + CRF
    k_logits<<<(BB * SS) / 8, 256>>>(cls_w, cls_b);
    k_crf<<<BB, 32>>>(labels, vlens, trans, start_t, end_t, out);
    k_loss<<<1, BB>>>(out);
}

// round 15
// speedup vs baseline: 1.2395x; 1.0799x over previous
#include <cuda_runtime.h>
#include <cuda_bf16.h>
#include <cstdint>
#include <math.h>

#define BB 64
#define SS 512
#define EE 256
#define HH 512
#define HDI 1024
#define G4 2048              // 4*H
#define NG 4096              // 2 dirs * 4H
#define TT 9
#define MR (BB*SS)           // 32768 rows

typedef __nv_bfloat16 bf16;

// ---------------- static device buffers ----------------
__device__ __align__(256) bf16  d_x0h[(size_t)MR * EE];
__device__ __align__(256) bf16  d_x0l[(size_t)MR * EE];
__device__ __align__(256) bf16  d_w0h[(size_t)NG * EE];
__device__ __align__(256) bf16  d_w0l[(size_t)NG * EE];
__device__ __align__(256) bf16  d_w1h[(size_t)NG * HDI];
__device__ __align__(256) bf16  d_w1l[(size_t)NG * HDI];
__device__ __align__(256) float d_xg0[(size_t)2 * SS * BB * G4];
__device__ __align__(256) float d_xg1[(size_t)2 * SS * BB * G4];
__device__ __align__(256) bf16  d_x1h[(size_t)MR * HDI];
__device__ __align__(256) bf16  d_x1l[(size_t)MR * HDI];
__device__ __align__(256) float d_x2[(size_t)MR * HDI];
__device__ __align__(256) bf16  d_hbh[2 * 2 * BB * HH];    // [dir][pp][m][k]
__device__ __align__(256) bf16  d_hbl[2 * 2 * BB * HH];
__device__ __align__(256) float d_logits[(size_t)MR * TT];
__device__ float d_llh[BB];
__device__ unsigned g_cnt2[2 * 32];                         // per-dir barrier (padded)
__device__ unsigned g_gen2[2 * 32];

// ---------------- helpers ----------------
__device__ __forceinline__ void split_bf(float x, bf16 &h, bf16 &l) {
    h = __float2bfloat16(x);
    l = __float2bfloat16(x - __bfloat162float(h));
}
__device__ __forceinline__ unsigned pack2(bf16 a, bf16 b) {
    __nv_bfloat162 v; v.x = a; v.y = b;
    return *(unsigned*)&v;
}
__device__ __forceinline__ float sig_fast(float x) {
    return __fdividef(1.f, 1.f + __expf(-x));
}
__device__ __forceinline__ float tanh_fast(float x) {
    return __fdividef(2.f, 1.f + __expf(-2.f * x)) - 1.f;
}
__device__ __forceinline__ void mma_bf16(float* c, unsigned a0, unsigned a1,
                                         unsigned a2, unsigned a3,
                                         unsigned b0, unsigned b1) {
    asm volatile(
        "mma.sync.aligned.m16n8k16.row.col.f32.bf16.bf16.f32 "
        "{%0,%1,%2,%3}, {%4,%5,%6,%7}, {%8,%9}, {%0,%1,%2,%3};"
        : "+f"(c[0]), "+f"(c[1]), "+f"(c[2]), "+f"(c[3])
        : "r"(a0), "r"(a1), "r"(a2), "r"(a3), "r"(b0), "r"(b1));
}
#define LDSM4(r0, r1, r2, r3, addr) \
    asm volatile("ldmatrix.sync.aligned.m8n8.x4.shared.b16 {%0,%1,%2,%3}, [%4];" \
        : "=r"(r0), "=r"(r1), "=r"(r2), "=r"(r3) : "r"(addr))
#define CPA16(dst_u32, src) \
    asm volatile("cp.async.cg.shared.global [%0], [%1], 16;" :: "r"(dst_u32), "l"(src))
#define CP_COMMIT() asm volatile("cp.async.commit_group;")
#define CP_WAIT1()  asm volatile("cp.async.wait_group 1;")
#define CP_WAIT0()  asm volatile("cp.async.wait_group 0;")

// ---------------- per-direction grid barrier (flat atomic-polling; best known) ----------------
__device__ __forceinline__ void grid_barrier_d(int d, int nb) {
    __syncthreads();
    if (threadIdx.x == 0) {
        unsigned* cnt = &g_cnt2[d * 32];
        unsigned* gen = &g_gen2[d * 32];
        __threadfence();
        unsigned g = atomicAdd(gen, 0u);
        unsigned r = atomicAdd(cnt, 1u);
        if (r == (unsigned)nb - 1u) {
            atomicExch(cnt, 0u);
            __threadfence();
            atomicAdd(gen, 1u);
        } else {
            while (atomicAdd(gen, 0u) == g) { __nanosleep(64); }
        }
        __threadfence();
    }
    __syncthreads();
}

// ---------------- embedding gather + bf16 split ----------------
__global__ void k_embed(const int* __restrict__ ids, const float* __restrict__ emb) {
    int row = blockIdx.x;
    int tid = threadIdx.x;                    // 64 threads, 4 cols each
    const float4* src = (const float4*)(emb + (size_t)ids[row] * EE);
    float4 v = src[tid];
    bf16 h0, l0, h1, l1, h2, l2, h3, l3;
    split_bf(v.x, h0, l0); split_bf(v.y, h1, l1);
    split_bf(v.z, h2, l2); split_bf(v.w, h3, l3);
    size_t o = (size_t)row * EE + 4 * tid;
    *(unsigned*)&d_x0h[o]     = pack2(h0, h1);
    *(unsigned*)&d_x0h[o + 2] = pack2(h2, h3);
    *(unsigned*)&d_x0l[o]     = pack2(l0, l1);
    *(unsigned*)&d_x0l[o + 2] = pack2(l2, l3);
}

// ---------------- weight split ----------------
__global__ void k_split(const float* __restrict__ src, bf16* __restrict__ h,
                        bf16* __restrict__ l, int n) {
    int i = blockIdx.x * blockDim.x + threadIdx.x;
    if (i < n) { bf16 a, b; split_bf(src[i], a, b); h[i] = a; l[i] = b; }
}

// ---------------- input-projection GEMM (3xBF16 mma + ldmatrix, 128x256 tile) ----------------
// Block 128(m) x 256(n), Kt=32, 16 warps (2x8), warp tile 64x32.
// Stage layout (rows x GST): Ah[128] Al[128] Wh[256] Wl[256] = 768 rows.
#define GST 40                                   // smem row stride (bf16 elems)
#define GSTAGE (768 * GST)                       // elems per stage
template <int PH>
__global__ void __launch_bounds__(512) k_gemm(const float* __restrict__ bih,
                                              const float* __restrict__ bhh) {
    constexpr int K = (PH == 0) ? EE : HDI;
    const bf16* Ah = (PH == 0) ? d_x0h : d_x1h;
    const bf16* Al = (PH == 0) ? d_x0l : d_x1l;
    const bf16* Wh = (PH == 0) ? d_w0h : d_w1h;
    const bf16* Wl = (PH == 0) ? d_w0l : d_w1l;
    float* xg      = (PH == 0) ? d_xg0 : d_xg1;

    extern __shared__ bf16 sm[];
    const unsigned sm_u32 = (unsigned)__cvta_generic_to_shared(sm);

    const int m0 = blockIdx.y * 128;
    const int n0 = blockIdx.x * 256;
    const int tid = threadIdx.x;
    const int wid = tid >> 5;
    const int lane = tid & 31;
    const int wm = (wid >> 3) * 64;              // 2 m-groups of 64
    const int wn = (wid & 7) * 32;               // 8 n-tiles of 32

    // ldmatrix lane offsets (bytes)
    const unsigned laneA = (((lane & 7) + ((lane >> 3) & 1) * 8) * GST + (lane >> 4) * 8) * 2;
    const unsigned laneB = (((lane & 7) + (lane >> 4) * 8) * GST + ((lane >> 3) & 1) * 8) * 2;

    float acc[4][4][4];
#pragma unroll
    for (int i = 0; i < 4; i++)
#pragma unroll
        for (int j = 0; j < 4; j++)
#pragma unroll
            for (int q = 0; q < 4; q++) acc[i][j][q] = 0.f;

    const bf16* gsrc[4] = {Ah, Al, Wh, Wl};
    const int rowbase[4] = {m0, m0, n0, n0};
    const int arrbase[4] = {0, 128 * GST, 256 * GST, 512 * GST};

    auto stage = [&](int s, int k0) {
#pragma unroll
        for (int i = 0; i < 6; i++) {
            int slot = tid + 512 * i;            // 0..3071
            int gr = slot >> 2;                  // 0..767
            int seg = slot & 3;
            int q = gr >> 7;                     // 0..5
            int arr = (q < 2) ? q : (q < 4) ? 2 : 3;
            int row = (q < 2) ? (gr & 127) : (gr & 255);
            const bf16* src = gsrc[arr] + (size_t)(rowbase[arr] + row) * K + k0 + seg * 8;
            unsigned dst = sm_u32 + (unsigned)((s * GSTAGE + arrbase[arr] + row * GST + seg * 8) * 2);
            CPA16(dst, src);
        }
        CP_COMMIT();
    };

    constexpr int KT = K / 32;
    stage(0, 0);
    stage(1, 32);
    for (int it = 0; it < KT; it++) {
        if (it + 1 < KT) { CP_WAIT1(); } else { CP_WAIT0(); }
        __syncthreads();
        if (it + 2 < KT) stage((it + 2) % 3, (it + 2) * 32);

        const unsigned sbase = sm_u32 + (unsigned)((it % 3) * GSTAGE * 2);
        const unsigned aAh = sbase + (unsigned)(wm * GST * 2) + laneA;
        const unsigned aAl = aAh + (unsigned)(128 * GST * 2);
        const unsigned aWh = sbase + (unsigned)(256 * GST * 2) + (unsigned)(wn * GST * 2) + laneB;
        const unsigned aWl = aWh + (unsigned)(256 * GST * 2);

#pragma unroll
        for (int kk = 0; kk < 32; kk += 16) {
            unsigned ah[4][4], al[4][4], bh[2][4], bl[2][4];
#pragma unroll
            for (int mi = 0; mi < 4; mi++) {
                unsigned off = (unsigned)(mi * 16 * GST * 2 + kk * 2);
                LDSM4(ah[mi][0], ah[mi][1], ah[mi][2], ah[mi][3], aAh + off);
                LDSM4(al[mi][0], al[mi][1], al[mi][2], al[mi][3], aAl + off);
            }
#pragma unroll
            for (int np = 0; np < 2; np++) {
                unsigned off = (unsigned)(np * 16 * GST * 2 + kk * 2);
                LDSM4(bh[np][0], bh[np][1], bh[np][2], bh[np][3], aWh + off);
                LDSM4(bl[np][0], bl[np][1], bl[np][2], bl[np][3], aWl + off);
            }
#pragma unroll
            for (int np = 0; np < 2; np++)
#pragma unroll
                for (int j = 0; j < 2; j++) {
                    int ni = np * 2 + j;
                    unsigned b0h = bh[np][2 * j], b1h = bh[np][2 * j + 1];
                    unsigned b0l = bl[np][2 * j], b1l = bl[np][2 * j + 1];
#pragma unroll
                    for (int mi = 0; mi < 4; mi++) {
                        mma_bf16(acc[mi][ni], ah[mi][0], ah[mi][1], ah[mi][2], ah[mi][3], b0h, b1h);
                        mma_bf16(acc[mi][ni], ah[mi][0], ah[mi][1], ah[mi][2], ah[mi][3], b0l, b1l);
                        mma_bf16(acc[mi][ni], al[mi][0], al[mi][1], al[mi][2], al[mi][3], b0h, b1h);
                    }
                }
        }
    }

    // epilogue: bias + scatter to xg[d][s][b][gate]
    const int fr2 = lane >> 2;
    const int fc2 = lane & 3;
#pragma unroll
    for (int ni = 0; ni < 4; ni++) {
        int ncol = n0 + wn + ni * 8 + 2 * fc2;
        float bias0 = bih[ncol] + bhh[ncol];
        float bias1 = bih[ncol + 1] + bhh[ncol + 1];
        int d = ncol >> 11;
        int gate = ncol & 2047;
#pragma unroll
        for (int mi = 0; mi < 4; mi++) {
#pragma unroll
            for (int half = 0; half < 2; half++) {
                int m = m0 + wm + mi * 16 + fr2 + half * 8;
                int b = m >> 9;
                int s = m & 511;
                float2 v;
                v.x = acc[mi][ni][half * 2 + 0] + bias0;
                v.y = acc[mi][ni][half * 2 + 1] + bias1;
                *(float2*)(xg + ((size_t)(d * SS + s) * BB + b) * G4 + gate) = v;
            }
        }
    }
}

// ---------------- persistent bidirectional LSTM scan (warp-private staging) ----------------
// 128 blocks: (dir, 8 hidden units). 128 threads (4 warps).
// Per step: G[64b][32c] = h[64][512] @ Wslice^T via m16n8k16, gates in-register.
// 4 chunks of k=128 in 3 rotating smem slots; warp-private staging, zero
// block-wide syncs inside the chunk loop. Fast MUFU-based gate math.
#define WST 520                                  // ws row stride
#define CST 136                                  // chunk row stride (128 + 8 pad)
#define WS_ELEMS (32 * WST)
#define CH_ELEMS (64 * CST)
template <int PH>
__global__ void __launch_bounds__(128, 1) k_scan(const float* __restrict__ whh, int nb) {
    extern __shared__ bf16 sm[];
    bf16* wsh = sm;                              // [32][WST]  c = g*8 + jj ordering
    bf16* wsl = sm + WS_ELEMS;
    const unsigned ws_u32 = (unsigned)__cvta_generic_to_shared(sm);
    const unsigned chk_u32 = ws_u32 + (unsigned)(2 * WS_ELEMS * 2);

    const float* xg = (PH == 0) ? d_xg0 : d_xg1;

    const int tid = threadIdx.x;
    const int d = blockIdx.x >> 6;
    const int j0 = (blockIdx.x & 63) * 8;

    // preload recurrent weight slice: ws[c][k], c = g*8 + jj
    for (int idx = tid; idx < 32 * HH; idx += 128) {
        int c = idx >> 9;
        int k = idx & 511;
        int g = c >> 3, jj = c & 7;
        float w = whh[((size_t)d * G4 + (size_t)g * HH + j0 + jj) * HH + k];
        bf16 h, l; split_bf(w, h, l);
        wsh[c * WST + k] = h;
        wsl[c * WST + k] = l;
    }
    // zero ping h (pp=0) for this block's 8 columns
    for (int idx = tid; idx < 64 * 4; idx += 128) {
        int m = idx >> 2, q = idx & 3;
        *(unsigned*)&d_hbh[((size_t)(d * 2 + 0) * BB + m) * HH + j0 + 2 * q] = 0u;
        *(unsigned*)&d_hbl[((size_t)(d * 2 + 0) * BB + m) * HH + j0 + 2 * q] = 0u;
    }
    grid_barrier_d(d, nb);

    const int lane = tid & 31;
    const int w = tid >> 5;
    const int fr = lane >> 2;
    const int fc = lane & 3;
    const int m1 = w * 16 + fr;                  // rows m1, m1+8
    const int u0 = 2 * fc;                       // units u0, u0+1

    // ldmatrix lane offsets (bytes)
    const unsigned laneA = (((lane & 7) + ((lane >> 3) & 1) * 8) * CST + (lane >> 4) * 8) * 2;
    const unsigned laneB = (((lane & 7) + (lane >> 4) * 8) * WST + ((lane >> 3) & 1) * 8) * 2;
    const unsigned aAbase = chk_u32 + (unsigned)(w * 16 * CST * 2) + laneA;

    float creg[4] = {0.f, 0.f, 0.f, 0.f};

    for (int t = 0; t < SS; t++) {
        const int tt = d ? (SS - 1 - t) : t;
        const bf16* hsh = d_hbh + ((size_t)(d * 2 + (t & 1)) * BB) * HH;
        const bf16* hsl = d_hbl + ((size_t)(d * 2 + (t & 1)) * BB) * HH;

        // warp-private stage: warp w copies ONLY rows [w*16, w*16+16) of chunk c
        auto stg = [&](int s, int c) {
            int k0 = c * 128;
            unsigned sb = chk_u32 + (unsigned)(s * 2 * CH_ELEMS * 2);
#pragma unroll
            for (int i = 0; i < 16; i++) {
                int slot = lane + 32 * i;        // 0..511 (warp's own work)
                int arr = slot >> 8;             // 0: hi, 1: lo
                int wi = slot & 255;
                int row16 = wi >> 4;             // 0..15
                int seg = wi & 15;               // k = k0 + seg*8
                int row = w * 16 + row16;
                const bf16* src = (arr ? hsl : hsh) + (size_t)row * HH + k0 + seg * 8;
                unsigned dst = sb + (unsigned)((arr * CH_ELEMS + row * CST + seg * 8) * 2);
                CPA16(dst, src);
            }
            CP_COMMIT();
        };
        stg(0, 0);
        stg(1, 1);

        // prefetch xg (independent of h)
        const float* xb = xg + (((size_t)d * SS + tt) * BB + m1) * G4 + j0 + u0;
        float2 xv[8];
#pragma unroll
        for (int g = 0; g < 4; g++) {
            xv[g * 2 + 0] = *(const float2*)(xb + (size_t)g * HH);
            xv[g * 2 + 1] = *(const float2*)(xb + (size_t)g * HH + (size_t)8 * G4);
        }

        float acc[4][4];
#pragma unroll
        for (int g = 0; g < 4; g++)
#pragma unroll
            for (int q = 0; q < 4; q++) acc[g][q] = 0.f;

        for (int c = 0; c < 4; c++) {
            if (c < 3) { CP_WAIT1(); } else { CP_WAIT0(); }
            __syncwarp();
            if (c + 2 < 4) stg((c + 2) % 3, c + 2);

            const unsigned aA = aAbase + (unsigned)((c % 3) * 2 * CH_ELEMS * 2);
            const unsigned aWb = ws_u32 + (unsigned)(c * 128 * 2) + laneB;
#pragma unroll
            for (int kk = 0; kk < 128; kk += 16) {
                unsigned a0, a1, a2, a3, c0, c1, c2, c3;
                LDSM4(a0, a1, a2, a3, aA + (unsigned)(kk * 2));
                LDSM4(c0, c1, c2, c3, aA + (unsigned)(CH_ELEMS * 2 + kk * 2));
#pragma unroll
                for (int np = 0; np < 2; np++) {
                    unsigned bh0, bh1, bh2, bh3, bl0, bl1, bl2, bl3;
                    unsigned off = (unsigned)(np * 16 * WST * 2 + kk * 2);
                    LDSM4(bh0, bh1, bh2, bh3, aWb + off);
                    LDSM4(bl0, bl1, bl2, bl3, aWb + (unsigned)(WS_ELEMS * 2) + off);
                    int n0i = np * 2;
                    mma_bf16(acc[n0i], a0, a1, a2, a3, bh0, bh1);
                    mma_bf16(acc[n0i], a0, a1, a2, a3, bl0, bl1);
                    mma_bf16(acc[n0i], c0, c1, c2, c3, bh0, bh1);
                    mma_bf16(acc[n0i + 1], a0, a1, a2, a3, bh2, bh3);
                    mma_bf16(acc[n0i + 1], a0, a1, a2, a3, bl2, bl3);
                    mma_bf16(acc[n0i + 1], c0, c1, c2, c3, bh2, bh3);
                }
            }
        }

        // gates: cell q -> (row m1 + 8*(q>>1), unit u0 + (q&1)), acc[g][q]
        float hn[4];
#pragma unroll
        for (int q = 0; q < 4; q++) {
            int rh = q >> 1;
            float xi = (q & 1) ? xv[0 + rh].y : xv[0 + rh].x;
            float xf = (q & 1) ? xv[2 + rh].y : xv[2 + rh].x;
            float xgv = (q & 1) ? xv[4 + rh].y : xv[4 + rh].x;
            float xo = (q & 1) ? xv[6 + rh].y : xv[6 + rh].x;
            float vi = acc[0][q] + xi;
            float vf = acc[1][q] + xf;
            float vg = acc[2][q] + xgv;
            float vo = acc[3][q] + xo;
            float si = sig_fast(vi);
            float sf = sig_fast(vf);
            float so = sig_fast(vo);
            float tg = tanh_fast(vg);
            creg[q] = sf * creg[q] + si * tg;
            hn[q] = so * tanh_fast(creg[q]);
        }

        // write h (hi/lo bf16) to pong buffer + layer output
        bf16 h0h, h0l, h1h, h1l, h2h, h2l, h3h, h3l;
        split_bf(hn[0], h0h, h0l); split_bf(hn[1], h1h, h1l);
        split_bf(hn[2], h2h, h2l); split_bf(hn[3], h3h, h3l);
        unsigned p0h = pack2(h0h, h1h), p0l = pack2(h0l, h1l);
        unsigned p1h = pack2(h2h, h3h), p1l = pack2(h2l, h3l);
        size_t hb = ((size_t)(d * 2 + ((t + 1) & 1)) * BB + m1) * HH + j0 + u0;
        *(unsigned*)&d_hbh[hb] = p0h;
        *(unsigned*)&d_hbl[hb] = p0l;
        *(unsigned*)&d_hbh[hb + (size_t)8 * HH] = p1h;
        *(unsigned*)&d_hbl[hb + (size_t)8 * HH] = p1l;

        if (PH == 0) {
            size_t xo1 = ((size_t)m1 * SS + tt) * HDI + d * HH + j0 + u0;
            *(unsigned*)&d_x1h[xo1] = p0h;
            *(unsigned*)&d_x1l[xo1] = p0l;
            size_t xo2 = ((size_t)(m1 + 8) * SS + tt) * HDI + d * HH + j0 + u0;
            *(unsigned*)&d_x1h[xo2] = p1h;
            *(unsigned*)&d_x1l[xo2] = p1l;
        } else {
            float2 v0; v0.x = hn[0]; v0.y = hn[1];
            float2 v1; v1.x = hn[2]; v1.y = hn[3];
            *(float2*)&d_x2[((size_t)m1 * SS + tt) * HDI + d * HH + j0 + u0] = v0;
            *(float2*)&d_x2[((size_t)(m1 + 8) * SS + tt) * HDI + d * HH + j0 + u0] = v1;
        }

        grid_barrier_d(d, nb);
    }
}

// ---------------- classifier ----------------
__global__ void k_logits(const float* __restrict__ clsw, const float* __restrict__ clsb) {
    int gwarp = (blockIdx.x * blockDim.x + threadIdx.x) >> 5;
    int lane = threadIdx.x & 31;
    if (gwarp >= BB * SS) return;
    const float4* xr = (const float4*)(d_x2 + (size_t)gwarp * HDI);
    float4 xv[8];
#pragma unroll
    for (int q = 0; q < 8; q++) xv[q] = xr[lane + 32 * q];
#pragma unroll
    for (int t = 0; t < TT; t++) {
        const float4* wr = (const float4*)(clsw + (size_t)t * HDI);
        float p = 0.f;
#pragma unroll
        for (int q = 0; q < 8; q++) {
            float4 wv = wr[lane + 32 * q];
            p += xv[q].x * wv.x + xv[q].y * wv.y + xv[q].z * wv.z + xv[q].w * wv.w;
        }
#pragma unroll
        for (int o = 16; o > 0; o >>= 1) p += __shfl_down_sync(0xffffffffu, p, o);
        if (lane == 0) d_logits[(size_t)gwarp * TT + t] = p + clsb[t];
    }
}

// ---------------- CRF ----------------
__global__ void k_crf(const int* __restrict__ labels, const int* __restrict__ vlens,
                      const float* __restrict__ trans, const float* __restrict__ startt,
                      const float* __restrict__ endt, float* __restrict__ out) {
    __shared__ float tr[TT * TT];
    __shared__ float alpha[TT], score[TT];
    __shared__ unsigned char hist[SS][TT];
    __shared__ float logZ_s;
    __shared__ int blast_s;

    const int b = blockIdx.x;
    const int tid = threadIdx.x;
    const int vl = vlens[b];
    const float* lg = d_logits + (size_t)b * SS * TT;
    const int* lab = labels + (size_t)b * SS;

    for (int i = tid; i < TT * TT; i += 32) tr[i] = trans[i];
    if (tid < TT) {
        float e = lg[tid];
        alpha[tid] = startt[tid] + e;
        score[tid] = startt[tid] + e;
    }
    __syncwarp();

    for (int t = 1; t < SS; t++) {
        float ns = 0.f, na = 0.f;
        int barg = 0;
        if (tid < TT) {
            float em = lg[t * TT + tid];
            float best = -1e30f, mx = -1e30f;
#pragma unroll
            for (int i = 0; i < TT; i++) {
                float v = score[i] + tr[i * TT + tid];
                if (v > best) { best = v; barg = i; }
                float a = alpha[i] + tr[i * TT + tid];
                mx = fmaxf(mx, a);
            }
            float ssum = 0.f;
#pragma unroll
            for (int i = 0; i < TT; i++) ssum += expf(alpha[i] + tr[i * TT + tid] - mx);
            ns = best + em;
            na = mx + logf(ssum) + em;
            hist[t][tid] = (unsigned char)barg;
        }
        __syncwarp();
        if (tid < TT && t < vl) { score[tid] = ns; alpha[tid] = na; }
        __syncwarp();
    }

    if (tid == 0) {
        float best = -1e30f, mx = -1e30f;
        int ba = 0;
        for (int j = 0; j < TT; j++) {
            float v = score[j] + endt[j];
            if (v > best) { best = v; ba = j; }
            mx = fmaxf(mx, alpha[j] + endt[j]);
        }
        float ss = 0.f;
        for (int j = 0; j < TT; j++) ss += expf(alpha[j] + endt[j] - mx);
        logZ_s = mx + logf(ss);
        blast_s = ba;
    }

    float np = 0.f;
    for (int t = 1 + tid; t < SS; t += 32) {
        if (t < vl) np += lg[t * TT + lab[t]] + tr[lab[t - 1] * TT + lab[t]];
    }
#pragma unroll
    for (int o = 16; o > 0; o >>= 1) np += __shfl_down_sync(0xffffffffu, np, o);
    __syncwarp();

    if (tid == 0) {
        float num = startt[lab[0]] + lg[lab[0]] + np + endt[lab[vl - 1]];
        d_llh[b] = num - logZ_s;
        int tag = blast_s;
        out[(size_t)b * SS + SS - 1] = (float)tag;
        for (int t = SS - 1; t >= 1; t--) {
            if (t < vl) tag = hist[t][tag];
            out[(size_t)b * SS + t - 1] = (float)tag;
        }
    }
}

__global__ void k_loss(float* __restrict__ out) {
    __shared__ float s[BB];
    s[threadIdx.x] = d_llh[threadIdx.x];
    __syncthreads();
    if (threadIdx.x == 0) {
        float t = 0.f;
        for (int i = 0; i < BB; i++) t += s[i];
        out[BB * SS] = -t / (float)BB;
    }
}

// ---------------- launch ----------------
extern "C" void kernel_launch(void* const* d_in, const int* in_sizes, int n_in,
                              void* d_out, int out_size) {
    const int*   ids    = (const int*)d_in[0];
    const int*   vlens  = (const int*)d_in[1];
    const int*   labels = (const int*)d_in[2];
    const float* emb    = (const float*)d_in[3];
    const float* w_ih0  = (const float*)d_in[4];
    const float* w_hh0  = (const float*)d_in[5];
    const float* b_ih0  = (const float*)d_in[6];
    const float* b_hh0  = (const float*)d_in[7];
    const float* w_ih1  = (const float*)d_in[8];
    const float* w_hh1  = (const float*)d_in[9];
    const float* b_ih1  = (const float*)d_in[10];
    const float* b_hh1  = (const float*)d_in[11];
    const float* cls_w  = (const float*)d_in[12];
    const float* cls_b  = (const float*)d_in[13];
    const float* trans  = (const float*)d_in[14];
    const float* start_t = (const float*)d_in[15];
    const float* end_t   = (const float*)d_in[16];
    float* out = (float*)d_out;

    const int GEMM_SMEM = 3 * GSTAGE * 2;                          // 184320 B
    const int SCAN_SMEM = (2 * WS_ELEMS + 3 * 2 * CH_ELEMS) * 2;   // 171008 B
    cudaFuncSetAttribute(k_gemm<0>, cudaFuncAttributeMaxDynamicSharedMemorySize, GEMM_SMEM);
    cudaFuncSetAttribute(k_gemm<1>, cudaFuncAttributeMaxDynamicSharedMemorySize, GEMM_SMEM);
    cudaFuncSetAttribute(k_scan<0>, cudaFuncAttributeMaxDynamicSharedMemorySize, SCAN_SMEM);
    cudaFuncSetAttribute(k_scan<1>, cudaFuncAttributeMaxDynamicSharedMemorySize, SCAN_SMEM);

    bf16 *w0h, *w0l, *w1h, *w1l;
    cudaGetSymbolAddress((void**)&w0h, d_w0h);
    cudaGetSymbolAddress((void**)&w0l, d_w0l);
    cudaGetSymbolAddress((void**)&w1h, d_w1h);
    cudaGetSymbolAddress((void**)&w1l, d_w1l);

    // prep: embedding + weight splits
    k_embed<<<BB * SS, 64>>>(ids, emb);
    k_split<<<(NG * EE + 255) / 256, 256>>>(w_ih0, w0h, w0l, NG * EE);
    k_split<<<(NG * HDI + 255) / 256, 256>>>(w_ih1, w1h, w1l, NG * HDI);

    dim3 ggrid(NG / 256, MR / 128);
    // layer 0
    k_gemm<0><<<ggrid, 512, GEMM_SMEM>>>(b_ih0, b_hh0);
    k_scan<0><<<128, 128, SCAN_SMEM>>>(w_hh0, 64);
    // layer 1
    k_gemm<1><<<ggrid, 512, GEMM_SMEM>>>(b_ih1, b_hh1);
    k_scan<1><<<128, 128, SCAN_SMEM>>>(w_hh1, 64);
    // classifier + CRF
    k_logits<<<(BB * SS) / 8, 256>>>(cls_w, cls_b);
    k_crf<<<BB, 32>>>(labels, vlens, trans, start_t, end_t, out);
    k_loss<<<1, BB>>>(out);
}